// round 1
// baseline (speedup 1.0000x reference)
#include <cuda_runtime.h>
#include <math.h>
#include <stdint.h>

#define LMAXV 10
#define NSH 121
#define MAXN 131072
#define HID 512

// ---------------- scratch (device globals; no allocations allowed) ----------------
__device__ float g_h8[(size_t)MAXN * 8];
__device__ float g_bufA[(size_t)MAXN * HID];
__device__ float g_bufB[(size_t)MAXN * HID];
__device__ float g_cs[(size_t)MAXN * 27];

// ---------------- compile-time SH constants ----------------
struct SHTab {
    float F[LMAXV + 1][LMAXV + 1];  // m==0: K(l,0); m>0: sqrt(2)*K(l,m)
    float DF[LMAXV + 1];            // dfact(2m-1)
};

constexpr double cfact(int n) {
    double r = 1.0;
    for (int i = 2; i <= n; ++i) r *= (double)i;
    return r;
}
constexpr double cdfact(int n) {
    double r = 1.0;
    while (n > 0) { r *= (double)n; n -= 2; }
    return r;
}
constexpr double csqrt(double x) {
    double g = (x > 1.0) ? x : 1.0;
    for (int i = 0; i < 200; ++i) g = 0.5 * (g + x / g);
    return g;
}
constexpr double PI_D = 3.14159265358979323846;

constexpr SHTab mk_shtab() {
    SHTab t{};
    for (int m = 0; m <= LMAXV; ++m) t.DF[m] = (float)cdfact(2 * m - 1);
    for (int l = 0; l <= LMAXV; ++l) {
        for (int m = 0; m <= l; ++m) {
            double K = csqrt((2.0 * l + 1.0) / (4.0 * PI_D) * cfact(l - m) / cfact(l + m));
            double f = (m == 0) ? K : csqrt(2.0) * K;
            t.F[l][m] = (float)f;
        }
    }
    return t;
}

__constant__ SHTab SHT = mk_shtab();

__constant__ float LAMB[LMAXV + 1] = {
    3.1415926535897927f, 2.0943951023931957f, 0.7853981633974483f, 0.0f,
    -0.13089969389957473f, 0.0f, 0.04908738521234052f, 0.0f,
    -0.024543692606170262f, 0.0f, 0.014317154020265985f
};

// ---------------- device math helpers ----------------
__device__ __forceinline__ float sigm(float x) { return 1.0f / (1.0f + expf(-x)); }
__device__ __forceinline__ float softplus_f(float x) {
    return fmaxf(x, 0.0f) + log1pf(expf(-fabsf(x)));
}

// Fully-unrolled real SH basis (e3nn ordering, integral norm, r^l omitted: inputs ~unit)
__device__ __forceinline__ void sh_eval(float x, float y, float z, float* Y) {
    float c[LMAXV + 1], s[LMAXV + 1];
    c[0] = 1.0f; s[0] = 0.0f;
#pragma unroll
    for (int m = 1; m <= LMAXV; ++m) {
        c[m] = x * c[m - 1] - y * s[m - 1];
        s[m] = x * s[m - 1] + y * c[m - 1];
    }
#pragma unroll
    for (int m = 0; m <= LMAXV; ++m) {
        float q2 = SHT.DF[m];  // Q[m,m]
        {
            const int l = m;
            float f = SHT.F[l][m];
            if (m == 0) {
                Y[l * l + l] = f * q2;
            } else {
                Y[l * l + l + m] = f * q2 * c[m];
                Y[l * l + l - m] = f * q2 * s[m];
            }
        }
        if (m < LMAXV) {
            float q1 = (float)(2 * m + 1) * z * q2;  // Q[m+1,m]
            {
                const int l = m + 1;
                float f = SHT.F[l][m];
                if (m == 0) {
                    Y[l * l + l] = f * q1;
                } else {
                    Y[l * l + l + m] = f * q1 * c[m];
                    Y[l * l + l - m] = f * q1 * s[m];
                }
            }
#pragma unroll
            for (int l = m + 2; l <= LMAXV; ++l) {
                float q = ((float)(2 * l - 1) * z * q1 - (float)(l + m - 1) * q2)
                          * (1.0f / (float)(l - m));
                float f = SHT.F[l][m];
                if (m == 0) {
                    Y[l * l + l] = f * q;
                } else {
                    Y[l * l + l + m] = f * q * c[m];
                    Y[l * l + l - m] = f * q * s[m];
                }
                q2 = q1; q1 = q;
            }
        }
    }
}

// ---------------- kernel 1: SH / irradiance / light / h8 ----------------
// out layout (floats): raw[0,3N) albedo[3N,6N) diffuse[6N,9N) specular[9N,12N)
//                      light[12N,15N) irradiance[15N,18N)
__global__ __launch_bounds__(128) void sh_kernel(
    const float* __restrict__ normals, const float* __restrict__ view_dirs,
    const float* __restrict__ feature, const float* __restrict__ refsh,
    float* __restrict__ out, float* __restrict__ h8, int N)
{
    int n = blockIdx.x * blockDim.x + threadIdx.x;
    if (n >= N) return;

    float nx = normals[3 * n + 0], ny = normals[3 * n + 1], nz = normals[3 * n + 2];
    float vx = view_dirs[3 * n + 0], vy = view_dirs[3 * n + 1], vz = view_dirs[3 * n + 2];
    float dt = nx * vx + ny * vy + nz * vz;
    float wx = 2.0f * nx * dt - vx;
    float wy = 2.0f * ny * dt - vy;
    float wz = 2.0f * nz * dt - vz;

    const float* f = feature + (size_t)n * 16;
    float rough = softplus_f(f[0]);
    float a0 = sigm(f[10]), a1 = sigm(f[11]), a2 = sigm(f[12]);

    const float* r = refsh + (size_t)n * (NSH * 3);
    float Y[NSH];

    // ---- pass 1: irradiance from normals ----
    {
        float inv = rsqrtf(nx * nx + ny * ny + nz * nz);
        sh_eval(nx * inv, ny * inv, nz * inv, Y);
    }
    float ix = 0.f, iy = 0.f, iz = 0.f;
    {
        int k = 0;
#pragma unroll
        for (int l = 0; l <= LMAXV; ++l) {
            float wl = LAMB[l];
#pragma unroll
            for (int j = 0; j < 2 * l + 1; ++j, ++k) {
                float w = Y[k] * wl;
                ix += w * r[3 * k + 0];
                iy += w * r[3 * k + 1];
                iz += w * r[3 * k + 2];
            }
        }
    }
    ix = fmaxf(ix, 0.f); iy = fmaxf(iy, 0.f); iz = fmaxf(iz, 0.f);

    // ---- pass 2: light from reflection dir with roughness decay ----
    {
        float inv = rsqrtf(wx * wx + wy * wy + wz * wz);
        sh_eval(wx * inv, wy * inv, wz * inv, Y);
    }
    float dec[LMAXV + 1];
    {
        float e = expf(-rough);
        float p = 1.0f;
        dec[0] = 1.0f;
#pragma unroll
        for (int l = 1; l <= LMAXV; ++l) { p *= e; dec[l] = dec[l - 1] * p; }
    }
    float lx = 0.f, ly = 0.f, lz = 0.f;
    {
        int k = 0;
#pragma unroll
        for (int l = 0; l <= LMAXV; ++l) {
            float wl = dec[l];
#pragma unroll
            for (int j = 0; j < 2 * l + 1; ++j, ++k) {
                float w = Y[k] * wl;
                lx += w * r[3 * k + 0];
                ly += w * r[3 * k + 1];
                lz += w * r[3 * k + 2];
            }
        }
    }
    lx = fmaxf(lx, 0.f); ly = fmaxf(ly, 0.f); lz = fmaxf(lz, 0.f);

    size_t N3 = 3 * (size_t)N;
    // albedo
    out[1 * N3 + 3 * n + 0] = a0;
    out[1 * N3 + 3 * n + 1] = a1;
    out[1 * N3 + 3 * n + 2] = a2;
    // diffuse
    out[2 * N3 + 3 * n + 0] = a0 * ix;
    out[2 * N3 + 3 * n + 1] = a1 * iy;
    out[2 * N3 + 3 * n + 2] = a2 * iz;
    // sh_light: light rows then irradiance rows
    out[4 * N3 + 3 * n + 0] = lx;
    out[4 * N3 + 3 * n + 1] = ly;
    out[4 * N3 + 3 * n + 2] = lz;
    out[5 * N3 + 3 * n + 0] = ix;
    out[5 * N3 + 3 * n + 1] = iy;
    out[5 * N3 + 3 * n + 2] = iz;

    // MLP input: [dot, v, n, rough]
    float* h = h8 + (size_t)n * 8;
    h[0] = dt; h[1] = vx; h[2] = vy; h[3] = vz;
    h[4] = nx; h[5] = ny; h[6] = nz; h[7] = rough;
}

// ---------------- kernel 2: layer0 (8 -> 512) ----------------
__global__ __launch_bounds__(256) void layer0_kernel(
    const float* __restrict__ h8, const float* __restrict__ w0,
    const float* __restrict__ b0, float* __restrict__ outp, int N)
{
    int idx = blockIdx.x * 256 + threadIdx.x;
    int n = idx >> 9;
    int j = idx & 511;
    if (n >= N) return;
    const float* a = h8 + (size_t)n * 8;
    float acc = b0[j];
#pragma unroll
    for (int i = 0; i < 8; ++i) acc = fmaf(a[i], w0[i * 512 + j], acc);
    outp[(size_t)n * 512 + j] = fmaxf(acc, 0.0f);
}

// ---------------- kernel 3: 512x512 layer GEMM (+bias, relu) ----------------
// A: [M,512] row-major, Bm: [512,512] row-major, C: [M,512]
__global__ __launch_bounds__(256) void gemm512_kernel(
    const float* __restrict__ A, const float* __restrict__ Bm,
    const float* __restrict__ bias, float* __restrict__ C, int M)
{
    __shared__ float As[16][128];
    __shared__ float Bs[16][128];

    int bx = blockIdx.x;           // N tile (0..3)
    int by = blockIdx.y;           // M tile
    int tid = threadIdx.x;
    int tm = tid >> 4;             // 0..15
    int tn = tid & 15;             // 0..15

    const float* Ab = A + (size_t)by * 128 * 512;
    const float* Bb = Bm + bx * 128;

    float acc[8][8];
#pragma unroll
    for (int i = 0; i < 8; ++i)
#pragma unroll
        for (int j = 0; j < 8; ++j) acc[i][j] = 0.0f;

    for (int k0 = 0; k0 < 512; k0 += 16) {
        // A tile: 128 rows x 16 k -> store transposed As[k][m]
#pragma unroll
        for (int t = 0; t < 2; ++t) {
            int i = tid + t * 256;          // 0..511 float4 slots
            int rr = i >> 2;                // 0..127
            int c4 = (i & 3) * 4;           // 0,4,8,12
            float4 v = *(const float4*)(Ab + (size_t)rr * 512 + k0 + c4);
            As[c4 + 0][rr] = v.x;
            As[c4 + 1][rr] = v.y;
            As[c4 + 2][rr] = v.z;
            As[c4 + 3][rr] = v.w;
        }
        // B tile: 16 rows x 128 cols
#pragma unroll
        for (int t = 0; t < 2; ++t) {
            int i = tid + t * 256;          // 0..511 float4 slots
            int rr = i >> 5;                // 0..15
            int c4 = (i & 31) * 4;          // 0..124
            float4 v = *(const float4*)(Bb + (size_t)(k0 + rr) * 512 + c4);
            *(float4*)&Bs[rr][c4] = v;
        }
        __syncthreads();

#pragma unroll
        for (int kk = 0; kk < 16; ++kk) {
            float af[8], bf[8];
#pragma unroll
            for (int i = 0; i < 8; ++i) af[i] = As[kk][tm * 8 + i];
#pragma unroll
            for (int j = 0; j < 8; ++j) bf[j] = Bs[kk][tn * 8 + j];
#pragma unroll
            for (int i = 0; i < 8; ++i)
#pragma unroll
                for (int j = 0; j < 8; ++j)
                    acc[i][j] = fmaf(af[i], bf[j], acc[i][j]);
        }
        __syncthreads();
    }

#pragma unroll
    for (int i = 0; i < 8; ++i) {
        int row = by * 128 + tm * 8 + i;
        float* Cr = C + (size_t)row * 512 + bx * 128 + tn * 8;
#pragma unroll
        for (int j = 0; j < 8; ++j) {
            float v = acc[i][j] + bias[bx * 128 + tn * 8 + j];
            Cr[j] = fmaxf(v, 0.0f);
        }
    }
}

// ---------------- kernel 4: final layer GEMM (512 -> 27, +bias, no relu) ----------------
__global__ __launch_bounds__(256) void gemm27_kernel(
    const float* __restrict__ A, const float* __restrict__ wc,
    const float* __restrict__ bc, float* __restrict__ cs, int M)
{
    __shared__ float As[16][128];
    __shared__ float Bs[16][32];

    int by = blockIdx.x;
    int tid = threadIdx.x;
    int tm = tid >> 4;   // 0..15 -> rows tm*8..
    int tn = tid & 15;   // 0..15 -> cols tn*2..

    const float* Ab = A + (size_t)by * 128 * 512;

    float acc[8][2];
#pragma unroll
    for (int i = 0; i < 8; ++i) { acc[i][0] = 0.f; acc[i][1] = 0.f; }

    for (int k0 = 0; k0 < 512; k0 += 16) {
#pragma unroll
        for (int t = 0; t < 2; ++t) {
            int i = tid + t * 256;
            int rr = i >> 2;
            int c4 = (i & 3) * 4;
            float4 v = *(const float4*)(Ab + (size_t)rr * 512 + k0 + c4);
            As[c4 + 0][rr] = v.x;
            As[c4 + 1][rr] = v.y;
            As[c4 + 2][rr] = v.z;
            As[c4 + 3][rr] = v.w;
        }
#pragma unroll
        for (int t = 0; t < 2; ++t) {
            int i = tid + t * 256;   // 0..511 covers 16x32
            int rr = i >> 5;         // 0..15
            int cc = i & 31;         // 0..31
            Bs[rr][cc] = (cc < 27) ? wc[(size_t)(k0 + rr) * 27 + cc] : 0.0f;
        }
        __syncthreads();

#pragma unroll
        for (int kk = 0; kk < 16; ++kk) {
            float af[8], bf[2];
#pragma unroll
            for (int i = 0; i < 8; ++i) af[i] = As[kk][tm * 8 + i];
            bf[0] = Bs[kk][tn * 2 + 0];
            bf[1] = Bs[kk][tn * 2 + 1];
#pragma unroll
            for (int i = 0; i < 8; ++i) {
                acc[i][0] = fmaf(af[i], bf[0], acc[i][0]);
                acc[i][1] = fmaf(af[i], bf[1], acc[i][1]);
            }
        }
        __syncthreads();
    }

#pragma unroll
    for (int i = 0; i < 8; ++i) {
        int row = by * 128 + tm * 8 + i;
#pragma unroll
        for (int j = 0; j < 2; ++j) {
            int col = tn * 2 + j;
            if (col < 27)
                cs[(size_t)row * 27 + col] = acc[i][j] + bc[col];
        }
    }
}

// ---------------- kernel 5: gate + specular + raw_rgb ----------------
__global__ __launch_bounds__(256) void finalize_kernel(
    const float* __restrict__ cs, const float* __restrict__ feature,
    float* __restrict__ out, int N)
{
    int n = blockIdx.x * 256 + threadIdx.x;
    if (n >= N) return;

    const float* f = feature + (size_t)n * 16;
    float coe[9];
#pragma unroll
    for (int i = 0; i < 9; ++i) coe[i] = f[1 + i];
    float sp0 = sigm(f[13]), sp1 = sigm(f[14]), sp2 = sigm(f[15]);

    const float* c = cs + (size_t)n * 27;
    float rr = 0.f, gg = 0.f, bb = 0.f;
#pragma unroll
    for (int i = 0; i < 9; ++i) {
        rr = fmaf(c[i], coe[i], rr);
        gg = fmaf(c[9 + i], coe[i], gg);
        bb = fmaf(c[18 + i], coe[i], bb);
    }
    float g0 = sigm(rr), g1 = sigm(gg), g2 = sigm(bb);

    size_t N3 = 3 * (size_t)N;
    float l0 = out[4 * N3 + 3 * n + 0];
    float l1 = out[4 * N3 + 3 * n + 1];
    float l2 = out[4 * N3 + 3 * n + 2];
    float d0 = out[2 * N3 + 3 * n + 0];
    float d1 = out[2 * N3 + 3 * n + 1];
    float d2 = out[2 * N3 + 3 * n + 2];

    float s0 = sp0 * l0 * g0;
    float s1 = sp1 * l1 * g1;
    float s2 = sp2 * l2 * g2;

    // specular
    out[3 * N3 + 3 * n + 0] = s0;
    out[3 * N3 + 3 * n + 1] = s1;
    out[3 * N3 + 3 * n + 2] = s2;
    // raw_rgb
    out[0 * N3 + 3 * n + 0] = d0 + s0;
    out[0 * N3 + 3 * n + 1] = d1 + s1;
    out[0 * N3 + 3 * n + 2] = d2 + s2;
}

// ---------------- launch ----------------
extern "C" void kernel_launch(void* const* d_in, const int* in_sizes, int n_in,
                              void* d_out, int out_size)
{
    const float* normals   = (const float*)d_in[0];
    const float* view_dirs = (const float*)d_in[1];
    const float* feature   = (const float*)d_in[2];
    const float* ref_SH    = (const float*)d_in[3];
    const float* w0 = (const float*)d_in[4];
    const float* b0 = (const float*)d_in[5];
    const float* w1 = (const float*)d_in[6];
    const float* b1 = (const float*)d_in[7];
    const float* w2 = (const float*)d_in[8];
    const float* b2 = (const float*)d_in[9];
    const float* w3 = (const float*)d_in[10];
    const float* b3 = (const float*)d_in[11];
    const float* wc = (const float*)d_in[12];
    const float* bc = (const float*)d_in[13];

    int N = in_sizes[0] / 3;
    float* out = (float*)d_out;

    float *h8p, *hA, *hB, *csp;
    cudaGetSymbolAddress((void**)&h8p, g_h8);
    cudaGetSymbolAddress((void**)&hA, g_bufA);
    cudaGetSymbolAddress((void**)&hB, g_bufB);
    cudaGetSymbolAddress((void**)&csp, g_cs);

    sh_kernel<<<(N + 127) / 128, 128>>>(normals, view_dirs, feature, ref_SH, out, h8p, N);
    layer0_kernel<<<(N * 512 + 255) / 256, 256>>>(h8p, w0, b0, hA, N);

    dim3 g512(4, N / 128);
    gemm512_kernel<<<g512, 256>>>(hA, w1, b1, hB, N);
    gemm512_kernel<<<g512, 256>>>(hB, w2, b2, hA, N);
    gemm512_kernel<<<g512, 256>>>(hA, w3, b3, hB, N);

    gemm27_kernel<<<N / 128, 256>>>(hB, wc, bc, csp, N);
    finalize_kernel<<<(N + 255) / 256, 256>>>(csp, feature, out, N);
}

// round 3
// speedup vs baseline: 5.1062x; 5.1062x over previous
#include <cuda_runtime.h>
#include <cuda_fp16.h>
#include <math.h>
#include <stdint.h>

#define LMAXV 10
#define NSH 121
#define MAXN 131072
#define HID 512

// ---------------- scratch (device globals; no allocations allowed) ----------------
__device__ __align__(16) float  g_h8[(size_t)MAXN * 8];
__device__ __align__(16) __half g_hA[(size_t)MAXN * HID];
__device__ __align__(16) __half g_hB[(size_t)MAXN * HID];
__device__ __align__(16) float  g_cs[(size_t)MAXN * 27];
__device__ __align__(16) __half g_wh[3][512 * 512];

// ---------------- compile-time SH constants ----------------
struct SHTab {
    float F[LMAXV + 1][LMAXV + 1];
    float DF[LMAXV + 1];
};
constexpr double cfact(int n) { double r = 1.0; for (int i = 2; i <= n; ++i) r *= (double)i; return r; }
constexpr double cdfact(int n) { double r = 1.0; while (n > 0) { r *= (double)n; n -= 2; } return r; }
constexpr double csqrt_(double x) { double g = (x > 1.0) ? x : 1.0; for (int i = 0; i < 200; ++i) g = 0.5 * (g + x / g); return g; }
constexpr double PI_D = 3.14159265358979323846;
constexpr SHTab mk_shtab() {
    SHTab t{};
    for (int m = 0; m <= LMAXV; ++m) t.DF[m] = (float)cdfact(2 * m - 1);
    for (int l = 0; l <= LMAXV; ++l)
        for (int m = 0; m <= l; ++m) {
            double K = csqrt_((2.0 * l + 1.0) / (4.0 * PI_D) * cfact(l - m) / cfact(l + m));
            t.F[l][m] = (float)((m == 0) ? K : csqrt_(2.0) * K);
        }
    return t;
}
__constant__ SHTab SHT = mk_shtab();
__constant__ float LAMB[LMAXV + 1] = {
    3.1415926535897927f, 2.0943951023931957f, 0.7853981633974483f, 0.0f,
    -0.13089969389957473f, 0.0f, 0.04908738521234052f, 0.0f,
    -0.024543692606170262f, 0.0f, 0.014317154020265985f
};

__device__ __forceinline__ float sigm(float x) { return 1.0f / (1.0f + expf(-x)); }
__device__ __forceinline__ float softplus_f(float x) { return fmaxf(x, 0.0f) + log1pf(expf(-fabsf(x))); }

__device__ __forceinline__ void sh_eval(float x, float y, float z, float* Y) {
    float c[LMAXV + 1], s[LMAXV + 1];
    c[0] = 1.0f; s[0] = 0.0f;
#pragma unroll
    for (int m = 1; m <= LMAXV; ++m) {
        c[m] = x * c[m - 1] - y * s[m - 1];
        s[m] = x * s[m - 1] + y * c[m - 1];
    }
#pragma unroll
    for (int m = 0; m <= LMAXV; ++m) {
        float q2 = SHT.DF[m];
        {
            const int l = m; float f = SHT.F[l][m];
            if (m == 0) Y[l * l + l] = f * q2;
            else { Y[l * l + l + m] = f * q2 * c[m]; Y[l * l + l - m] = f * q2 * s[m]; }
        }
        if (m < LMAXV) {
            float q1 = (float)(2 * m + 1) * z * q2;
            {
                const int l = m + 1; float f = SHT.F[l][m];
                if (m == 0) Y[l * l + l] = f * q1;
                else { Y[l * l + l + m] = f * q1 * c[m]; Y[l * l + l - m] = f * q1 * s[m]; }
            }
#pragma unroll
            for (int l = m + 2; l <= LMAXV; ++l) {
                float q = ((float)(2 * l - 1) * z * q1 - (float)(l + m - 1) * q2) * (1.0f / (float)(l - m));
                float f = SHT.F[l][m];
                if (m == 0) Y[l * l + l] = f * q;
                else { Y[l * l + l + m] = f * q * c[m]; Y[l * l + l - m] = f * q * s[m]; }
                q2 = q1; q1 = q;
            }
        }
    }
}

// ---------------- kernel 1: SH / irradiance / light / h8 ----------------
__global__ __launch_bounds__(128) void sh_kernel(
    const float* __restrict__ normals, const float* __restrict__ view_dirs,
    const float* __restrict__ feature, const float* __restrict__ refsh,
    float* __restrict__ out, float* __restrict__ h8, int N)
{
    int n = blockIdx.x * blockDim.x + threadIdx.x;
    if (n >= N) return;

    float nx = normals[3 * n + 0], ny = normals[3 * n + 1], nz = normals[3 * n + 2];
    float vx = view_dirs[3 * n + 0], vy = view_dirs[3 * n + 1], vz = view_dirs[3 * n + 2];
    float dt = nx * vx + ny * vy + nz * vz;
    float wx = 2.0f * nx * dt - vx;
    float wy = 2.0f * ny * dt - vy;
    float wz = 2.0f * nz * dt - vz;

    const float* f = feature + (size_t)n * 16;
    float rough = softplus_f(f[0]);
    float a0 = sigm(f[10]), a1 = sigm(f[11]), a2 = sigm(f[12]);

    const float* r = refsh + (size_t)n * (NSH * 3);
    float Y[NSH];

    { float inv = rsqrtf(nx * nx + ny * ny + nz * nz); sh_eval(nx * inv, ny * inv, nz * inv, Y); }
    float ix = 0.f, iy = 0.f, iz = 0.f;
    {
        int k = 0;
#pragma unroll
        for (int l = 0; l <= LMAXV; ++l) {
            float wl = LAMB[l];
#pragma unroll
            for (int j = 0; j < 2 * l + 1; ++j, ++k) {
                float w = Y[k] * wl;
                ix += w * r[3 * k + 0]; iy += w * r[3 * k + 1]; iz += w * r[3 * k + 2];
            }
        }
    }
    ix = fmaxf(ix, 0.f); iy = fmaxf(iy, 0.f); iz = fmaxf(iz, 0.f);

    { float inv = rsqrtf(wx * wx + wy * wy + wz * wz); sh_eval(wx * inv, wy * inv, wz * inv, Y); }
    float dec[LMAXV + 1];
    {
        float e = expf(-rough); float p = 1.0f; dec[0] = 1.0f;
#pragma unroll
        for (int l = 1; l <= LMAXV; ++l) { p *= e; dec[l] = dec[l - 1] * p; }
    }
    float lx = 0.f, ly = 0.f, lz = 0.f;
    {
        int k = 0;
#pragma unroll
        for (int l = 0; l <= LMAXV; ++l) {
            float wl = dec[l];
#pragma unroll
            for (int j = 0; j < 2 * l + 1; ++j, ++k) {
                float w = Y[k] * wl;
                lx += w * r[3 * k + 0]; ly += w * r[3 * k + 1]; lz += w * r[3 * k + 2];
            }
        }
    }
    lx = fmaxf(lx, 0.f); ly = fmaxf(ly, 0.f); lz = fmaxf(lz, 0.f);

    size_t N3 = 3 * (size_t)N;
    out[1 * N3 + 3 * n + 0] = a0;      out[1 * N3 + 3 * n + 1] = a1;      out[1 * N3 + 3 * n + 2] = a2;
    out[2 * N3 + 3 * n + 0] = a0 * ix; out[2 * N3 + 3 * n + 1] = a1 * iy; out[2 * N3 + 3 * n + 2] = a2 * iz;
    out[4 * N3 + 3 * n + 0] = lx;      out[4 * N3 + 3 * n + 1] = ly;      out[4 * N3 + 3 * n + 2] = lz;
    out[5 * N3 + 3 * n + 0] = ix;      out[5 * N3 + 3 * n + 1] = iy;      out[5 * N3 + 3 * n + 2] = iz;

    float* h = h8 + (size_t)n * 8;
    h[0] = dt; h[1] = vx; h[2] = vy; h[3] = vz;
    h[4] = nx; h[5] = ny; h[6] = nz; h[7] = rough;
}

// ---------------- kernel 2: layer0 (8 -> 512), fp16 out ----------------
__global__ __launch_bounds__(256) void layer0_kernel(
    const float* __restrict__ h8, const float* __restrict__ w0,
    const float* __restrict__ b0, __half* __restrict__ outp, int N)
{
    int idx = blockIdx.x * 256 + threadIdx.x;
    int n = idx >> 9;
    int j = idx & 511;
    if (n >= N) return;
    const float* a = h8 + (size_t)n * 8;
    float acc = b0[j];
#pragma unroll
    for (int i = 0; i < 8; ++i) acc = fmaf(a[i], w0[i * 512 + j], acc);
    outp[(size_t)n * 512 + j] = __float2half_rn(fmaxf(acc, 0.0f));
}

// ---------------- weight fp32 -> fp16 ----------------
__global__ __launch_bounds__(256) void cvtw_kernel(
    const float* __restrict__ w1, const float* __restrict__ w2,
    const float* __restrict__ w3, __half* __restrict__ o)
{
    int i = blockIdx.x * 256 + threadIdx.x;           // 0 .. 3*262144-1
    const float* src = (i < 262144) ? w1 : (i < 524288) ? w2 : w3;
    int j = i & 262143;
    o[i] = __float2half_rn(src[j]);
}

// ---------------- fp16 mma.sync GEMM: C[M,512] = relu(A[M,512] @ W[512,512] + bias) ----
// CTA tile: BM=128, BN=128, BK=32; 8 warps, warp tile 32x64. 3-stage cp.async.
__device__ __forceinline__ uint32_t smem_u32(const void* p) {
    uint32_t a;
    asm("{ .reg .u64 t; cvta.to.shared.u64 t, %1; cvt.u32.u64 %0, t; }" : "=r"(a) : "l"(p));
    return a;
}
__device__ __forceinline__ void cp16(uint32_t dst, const void* src) {
    asm volatile("cp.async.cg.shared.global [%0], [%1], 16;\n" :: "r"(dst), "l"(src));
}
#define LDSM4(r0, r1, r2, r3, addr) \
    asm volatile("ldmatrix.sync.aligned.m8n8.x4.shared.b16 {%0,%1,%2,%3}, [%4];" \
                 : "=r"(r0), "=r"(r1), "=r"(r2), "=r"(r3) : "r"(addr))
#define LDSM4T(r0, r1, r2, r3, addr) \
    asm volatile("ldmatrix.sync.aligned.m8n8.x4.trans.shared.b16 {%0,%1,%2,%3}, [%4];" \
                 : "=r"(r0), "=r"(r1), "=r"(r2), "=r"(r3) : "r"(addr))
#define MMA16816(d, a, b0v, b1v) \
    asm volatile("mma.sync.aligned.m16n8k16.row.col.f32.f16.f16.f32 " \
                 "{%0,%1,%2,%3}, {%4,%5,%6,%7}, {%8,%9}, {%0,%1,%2,%3};" \
                 : "+f"((d)[0]), "+f"((d)[1]), "+f"((d)[2]), "+f"((d)[3]) \
                 : "r"((a)[0]), "r"((a)[1]), "r"((a)[2]), "r"((a)[3]), "r"(b0v), "r"(b1v))

#define SA_STAGE 10240     // 128 rows * 80 B
#define SB_STAGE 8192      // 32 rows * 256 B
#define SB_BASE  30720     // 3 * SA_STAGE
#define SM_MMA   55296     // SB_BASE + 3 * SB_STAGE

__device__ __forceinline__ void mma_load_stage(int kt, int tid, uint32_t sb,
                                               const __half* Ab, const __half* Wb)
{
    int s = kt % 3;
    uint32_t sa = sb + s * SA_STAGE;
    uint32_t sbm = sb + SB_BASE + s * SB_STAGE;
    int k0 = kt * 32;
#pragma unroll
    for (int t = 0; t < 2; ++t) {
        int i = tid + t * 256;
        int r = i >> 2, c = i & 3;                 // 128 rows x 4 chunks(16B)
        cp16(sa + (uint32_t)(r * 80 + c * 16), Ab + (size_t)r * 512 + k0 + c * 8);
    }
#pragma unroll
    for (int t = 0; t < 2; ++t) {
        int i = tid + t * 256;
        int r = i >> 4, c8 = i & 15;               // 32 rows x 16 chunks(16B), swizzled
        cp16(sbm + (uint32_t)((r * 16 + (c8 ^ (r & 7))) * 16),
             Wb + (size_t)(k0 + r) * 512 + c8 * 8);
    }
    asm volatile("cp.async.commit_group;\n" ::: "memory");
}

__global__ __launch_bounds__(256, 2)
void mma512_kernel(const __half* __restrict__ A, const __half* __restrict__ W,
                   const float* __restrict__ bias, __half* __restrict__ C)
{
    extern __shared__ __align__(128) char smem[];
    uint32_t sb = smem_u32(smem);
    int tid = threadIdx.x, l = tid & 31, w = tid >> 5;
    int bx = blockIdx.x, by = blockIdx.y;
    int wm = (w >> 1) * 32, wn = (w & 1) * 64;

    const __half* Ab = A + (size_t)by * 128 * 512;
    const __half* Wb = W + bx * 128;

    float acc[2][8][4];
#pragma unroll
    for (int i = 0; i < 2; ++i)
#pragma unroll
        for (int j = 0; j < 8; ++j)
#pragma unroll
            for (int q = 0; q < 4; ++q) acc[i][j][q] = 0.0f;

    // per-lane ldmatrix address components
    uint32_t la = (uint32_t)((wm + (l & 7) + ((l >> 3) & 1) * 8) * 80 + ((l >> 4) & 1) * 16);
    int rb = (l & 7) + ((l >> 3) & 1) * 8;
    uint32_t lb[4];
#pragma unroll
    for (int p = 0; p < 4; ++p) {
        int c8b = (wn >> 3) + p * 2 + ((l >> 4) & 1);
        lb[p] = (uint32_t)(rb * 256 + ((c8b ^ (rb & 7)) * 16));
    }

    mma_load_stage(0, tid, sb, Ab, Wb);
    mma_load_stage(1, tid, sb, Ab, Wb);

#pragma unroll 4
    for (int kt = 0; kt < 16; ++kt) {
        if (kt < 14) asm volatile("cp.async.wait_group 1;\n" ::: "memory");
        else         asm volatile("cp.async.wait_group 0;\n" ::: "memory");
        __syncthreads();
        if (kt < 14) mma_load_stage(kt + 2, tid, sb, Ab, Wb);

        int s = kt % 3;
        uint32_t sa = sb + s * SA_STAGE + la;
        uint32_t sbm = sb + SB_BASE + s * SB_STAGE;
#pragma unroll
        for (int kk = 0; kk < 2; ++kk) {
            uint32_t a0[4], a1[4];
            LDSM4(a0[0], a0[1], a0[2], a0[3], sa + kk * 32);
            LDSM4(a1[0], a1[1], a1[2], a1[3], sa + 1280 + kk * 32);
#pragma unroll
            for (int p = 0; p < 4; ++p) {
                uint32_t b0, b1, b2, b3;
                LDSM4T(b0, b1, b2, b3, sbm + kk * 4096 + lb[p]);
                MMA16816(acc[0][p * 2 + 0], a0, b0, b1);
                MMA16816(acc[0][p * 2 + 1], a0, b2, b3);
                MMA16816(acc[1][p * 2 + 0], a1, b0, b1);
                MMA16816(acc[1][p * 2 + 1], a1, b2, b3);
            }
        }
    }

    // epilogue: bias + relu -> fp16
#pragma unroll
    for (int mt = 0; mt < 2; ++mt) {
        int row = by * 128 + wm + mt * 16 + (l >> 2);
#pragma unroll
        for (int nt = 0; nt < 8; ++nt) {
            int col = bx * 128 + wn + nt * 8 + (l & 3) * 2;
            float bs0 = __ldg(bias + col), bs1 = __ldg(bias + col + 1);
            float* d = acc[mt][nt];
            __half2 h01 = __floats2half2_rn(fmaxf(d[0] + bs0, 0.0f), fmaxf(d[1] + bs1, 0.0f));
            __half2 h23 = __floats2half2_rn(fmaxf(d[2] + bs0, 0.0f), fmaxf(d[3] + bs1, 0.0f));
            *(__half2*)(C + (size_t)row * 512 + col) = h01;
            *(__half2*)(C + (size_t)(row + 8) * 512 + col) = h23;
        }
    }
}

// ---------------- kernel 4: final layer (512 -> 27, +bias, no relu), fp16 A ----------------
__global__ __launch_bounds__(256) void gemm27_kernel(
    const __half* __restrict__ A, const float* __restrict__ wc,
    const float* __restrict__ bc, float* __restrict__ cs, int M)
{
    __shared__ float As[16][128];
    __shared__ float Bs[16][32];

    int by = blockIdx.x;
    int tid = threadIdx.x;
    int tm = tid >> 4;
    int tn = tid & 15;

    const __half* Ab = A + (size_t)by * 128 * 512;

    float acc[8][2];
#pragma unroll
    for (int i = 0; i < 8; ++i) { acc[i][0] = 0.f; acc[i][1] = 0.f; }

    for (int k0 = 0; k0 < 512; k0 += 16) {
#pragma unroll
        for (int t = 0; t < 2; ++t) {
            int i = tid + t * 256;
            int rr = i >> 2;
            int c4 = (i & 3) * 4;
            // 4 halves = 8 bytes
            uint2 u = *(const uint2*)(Ab + (size_t)rr * 512 + k0 + c4);
            __half2 p0 = *(__half2*)&u.x;
            __half2 p1 = *(__half2*)&u.y;
            float2 f0 = __half22float2(p0);
            float2 f1 = __half22float2(p1);
            As[c4 + 0][rr] = f0.x; As[c4 + 1][rr] = f0.y;
            As[c4 + 2][rr] = f1.x; As[c4 + 3][rr] = f1.y;
        }
#pragma unroll
        for (int t = 0; t < 2; ++t) {
            int i = tid + t * 256;
            int rr = i >> 5;
            int cc = i & 31;
            Bs[rr][cc] = (cc < 27) ? wc[(size_t)(k0 + rr) * 27 + cc] : 0.0f;
        }
        __syncthreads();

#pragma unroll
        for (int kk = 0; kk < 16; ++kk) {
            float af[8], bf[2];
#pragma unroll
            for (int i = 0; i < 8; ++i) af[i] = As[kk][tm * 8 + i];
            bf[0] = Bs[kk][tn * 2 + 0];
            bf[1] = Bs[kk][tn * 2 + 1];
#pragma unroll
            for (int i = 0; i < 8; ++i) {
                acc[i][0] = fmaf(af[i], bf[0], acc[i][0]);
                acc[i][1] = fmaf(af[i], bf[1], acc[i][1]);
            }
        }
        __syncthreads();
    }

#pragma unroll
    for (int i = 0; i < 8; ++i) {
        int row = by * 128 + tm * 8 + i;
#pragma unroll
        for (int j = 0; j < 2; ++j) {
            int col = tn * 2 + j;
            if (col < 27)
                cs[(size_t)row * 27 + col] = acc[i][j] + bc[col];
        }
    }
}

// ---------------- kernel 5: gate + specular + raw_rgb ----------------
__global__ __launch_bounds__(256) void finalize_kernel(
    const float* __restrict__ cs, const float* __restrict__ feature,
    float* __restrict__ out, int N)
{
    int n = blockIdx.x * 256 + threadIdx.x;
    if (n >= N) return;

    const float* f = feature + (size_t)n * 16;
    float coe[9];
#pragma unroll
    for (int i = 0; i < 9; ++i) coe[i] = f[1 + i];
    float sp0 = sigm(f[13]), sp1 = sigm(f[14]), sp2 = sigm(f[15]);

    const float* c = cs + (size_t)n * 27;
    float rr = 0.f, gg = 0.f, bb = 0.f;
#pragma unroll
    for (int i = 0; i < 9; ++i) {
        rr = fmaf(c[i], coe[i], rr);
        gg = fmaf(c[9 + i], coe[i], gg);
        bb = fmaf(c[18 + i], coe[i], bb);
    }
    float g0 = sigm(rr), g1 = sigm(gg), g2 = sigm(bb);

    size_t N3 = 3 * (size_t)N;
    float l0 = out[4 * N3 + 3 * n + 0];
    float l1 = out[4 * N3 + 3 * n + 1];
    float l2 = out[4 * N3 + 3 * n + 2];
    float d0 = out[2 * N3 + 3 * n + 0];
    float d1 = out[2 * N3 + 3 * n + 1];
    float d2 = out[2 * N3 + 3 * n + 2];

    float s0 = sp0 * l0 * g0;
    float s1 = sp1 * l1 * g1;
    float s2 = sp2 * l2 * g2;

    out[3 * N3 + 3 * n + 0] = s0;
    out[3 * N3 + 3 * n + 1] = s1;
    out[3 * N3 + 3 * n + 2] = s2;
    out[0 * N3 + 3 * n + 0] = d0 + s0;
    out[0 * N3 + 3 * n + 1] = d1 + s1;
    out[0 * N3 + 3 * n + 2] = d2 + s2;
}

// ---------------- launch ----------------
extern "C" void kernel_launch(void* const* d_in, const int* in_sizes, int n_in,
                              void* d_out, int out_size)
{
    const float* normals   = (const float*)d_in[0];
    const float* view_dirs = (const float*)d_in[1];
    const float* feature   = (const float*)d_in[2];
    const float* ref_SH    = (const float*)d_in[3];
    const float* w0 = (const float*)d_in[4];
    const float* b0 = (const float*)d_in[5];
    const float* w1 = (const float*)d_in[6];
    const float* b1 = (const float*)d_in[7];
    const float* w2 = (const float*)d_in[8];
    const float* b2 = (const float*)d_in[9];
    const float* w3 = (const float*)d_in[10];
    const float* b3 = (const float*)d_in[11];
    const float* wc = (const float*)d_in[12];
    const float* bc = (const float*)d_in[13];

    int N = in_sizes[0] / 3;
    float* out = (float*)d_out;

    float *h8p, *csp;
    __half *hA, *hB, *whp;
    cudaGetSymbolAddress((void**)&h8p, g_h8);
    cudaGetSymbolAddress((void**)&hA, g_hA);
    cudaGetSymbolAddress((void**)&hB, g_hB);
    cudaGetSymbolAddress((void**)&csp, g_cs);
    cudaGetSymbolAddress((void**)&whp, g_wh);

    cudaFuncSetAttribute(mma512_kernel, cudaFuncAttributeMaxDynamicSharedMemorySize, SM_MMA);

    __half* w1h = whp + 0 * 262144;
    __half* w2h = whp + 1 * 262144;
    __half* w3h = whp + 2 * 262144;

    cvtw_kernel<<<3 * 262144 / 256, 256>>>(w1, w2, w3, whp);
    sh_kernel<<<(N + 127) / 128, 128>>>(normals, view_dirs, feature, ref_SH, out, h8p, N);
    layer0_kernel<<<(N * 512 + 255) / 256, 256>>>(h8p, w0, b0, hA, N);

    dim3 gm(4, N / 128);
    mma512_kernel<<<gm, 256, SM_MMA>>>(hA, w1h, b1, hB);
    mma512_kernel<<<gm, 256, SM_MMA>>>(hB, w2h, b2, hA);
    mma512_kernel<<<gm, 256, SM_MMA>>>(hA, w3h, b3, hB);

    gemm27_kernel<<<N / 128, 256>>>(hB, wc, bc, csp, N);
    finalize_kernel<<<(N + 255) / 256, 256>>>(csp, feature, out, N);
}